// round 14
// baseline (speedup 1.0000x reference)
#include <cuda_runtime.h>

typedef unsigned long long ull;

// ---- SoA weight planes + quad FF table ----
__device__ __align__(16) float g_w1c[16],  g_w1s[16];    // [co*4 + i*2 + j]
__device__ __align__(16) float g_w2c[544], g_w2s[544];   // [co*68 + c*16+i*4+j]
__device__ __align__(16) float4 g_wfq[2880];             // [o*288 + f] = (c,s,s,c)

__global__ void prep_kernel(const float* __restrict__ w1,
                            const float* __restrict__ w2,
                            const float* __restrict__ wf) {
    int gt = blockIdx.x * blockDim.x + threadIdx.x;
    for (int i = gt; i < 3408; i += gridDim.x * blockDim.x) {
        if (i < 16) {
            float s, c; __sincosf(w1[i], &s, &c);
            g_w1c[i] = c; g_w1s[i] = s;
        } else if (i < 528) {
            int k = i - 16;
            int co = k >> 6, r = k & 63;
            float s, c; __sincosf(w2[k], &s, &c);
            g_w2c[co * 68 + r] = c; g_w2s[co * 68 + r] = s;
        } else {
            int k = i - 528;
            int f = k / 10, o = k % 10;
            float s, c; __sincosf(wf[k], &s, &c);
            g_wfq[o * 288 + f] = make_float4(c, s, s, c);
        }
    }
}

// packed dual-FMA: acc(lo,hi) += a(lo,hi) * b(lo,hi)
static __device__ __forceinline__ void ffma2(ull& acc, ull a, ull b) {
    asm("fma.rn.f32x2 %0, %1, %2, %0;" : "+l"(acc) : "l"(a), "l"(b));
}
static __device__ __forceinline__ float f2lo(ull v) { return __uint_as_float((unsigned)v); }
static __device__ __forceinline__ float f2hi(ull v) { return __uint_as_float((unsigned)(v >> 32)); }

// FMA-pipe sincos (R4-proven: beats MUFU bursts for bulk pixel trig)
static __device__ __forceinline__ void fast_sincos(float x, float& s, float& c) {
    float t = fmaf(x, 0.63661977236758134f, 12582912.0f);
    unsigned q = __float_as_uint(t);
    float kf = t - 12582912.0f;
    float r = fmaf(kf, -1.57079625129699707031f, x);
    r = fmaf(kf, -7.54978941586159e-08f, r);
    float y = r * r;
    float ps = fmaf(y, -1.95152959e-4f, 8.33216087e-3f);
    ps = fmaf(y, ps, -1.66666546e-1f);
    float s0 = fmaf(r * y, ps, r);
    float pc = fmaf(y, 2.44331571e-5f, -1.38873162e-3f);
    pc = fmaf(y, pc, 4.16666232e-2f);
    pc = fmaf(y, pc, -0.5f);
    float c0 = fmaf(y, pc, 1.0f);
    bool sw = q & 1u;
    float ss = sw ? c0 : s0;
    float cc = sw ? s0 : c0;
    unsigned sgs = (q & 2u) << 30;
    unsigned sgc = ((q + 1u) & 2u) << 30;
    s = __uint_as_float(__float_as_uint(ss) ^ sgs);
    c = __uint_as_float(__float_as_uint(cc) ^ sgc);
}

// single-instruction MUFU rsqrt (amortized use, MUFU pipe idle)
static __device__ __forceinline__ float mufu_rsqrt(float d) {
    float r;
    asm("rsqrt.approx.f32 %0, %1;" : "=f"(r) : "f"(d));
    return r;
}

__global__ __launch_bounds__(320, 4) void ring_kernel(const float* __restrict__ x,
                                                      float* __restrict__ out) {
    __shared__ __align__(16) float s_pxc[784], s_pxs[784];   // pixel planes 28x28
    __shared__ __align__(16) float s_h1c[896], s_h1s[896];   // [co*224 + py*16 + px]
    __shared__ __align__(16) float2 s_h2[288];               // [(ho*6+wo)*8 + co]
    __shared__ __align__(16) float s_w1c[16],  s_w1s[16];
    __shared__ __align__(16) float s_w2c[544], s_w2s[544];

    const int tid = threadIdx.x;

    // ---- Stage 0: pixel trig (poly, FMA pipe) + weight staging ----
    const float4* xb4 = reinterpret_cast<const float4*>(x + (size_t)blockIdx.x * 784);
    for (int i = tid; i < 196; i += 320) {
        float4 v = xb4[i];
        float s0, c0, s1, c1, s2, c2, s3, c3;
        fast_sincos(v.x, s0, c0);
        fast_sincos(v.y, s1, c1);
        fast_sincos(v.z, s2, c2);
        fast_sincos(v.w, s3, c3);
        *reinterpret_cast<float4*>(&s_pxc[4 * i]) = make_float4(c0, c1, c2, c3);
        *reinterpret_cast<float4*>(&s_pxs[4 * i]) = make_float4(s0, s1, s2, s3);
    }
    if (tid < 16) { s_w1c[tid] = g_w1c[tid]; s_w1s[tid] = g_w1s[tid]; }
    for (int i = tid; i < 544; i += 320) { s_w2c[i] = g_w2c[i]; s_w2s[i] = g_w2s[i]; }
    __syncthreads();

    // ---- Stage 1: conv1 2x2 s2 -> 14x14x4; one spatial pos/thread, 4 co ----
    if (tid < 196) {
        int py = tid / 14, px = tid % 14;
        int base = py * 56 + px * 2;
        ull vc0 = *(const ull*)&s_pxc[base];
        ull vc1 = *(const ull*)&s_pxc[base + 28];
        ull vs0 = *(const ull*)&s_pxs[base];
        ull vs1 = *(const ull*)&s_pxs[base + 28];
        int dst = py * 16 + px;
#pragma unroll
        for (int co = 0; co < 4; co++) {
            ulonglong2 wc = *(const ulonglong2*)&s_w1c[co * 4];
            ulonglong2 ws = *(const ulonglong2*)&s_w1s[co * 4];
            ull S = 0, T3 = 0, T4 = 0;
            ffma2(S,  vc0, wc.x); ffma2(S,  vc1, wc.y);
            ffma2(S,  vs0, ws.x); ffma2(S,  vs1, ws.y);
            ffma2(T3, vs0, wc.x); ffma2(T3, vs1, wc.y);
            ffma2(T4, vc0, ws.x); ffma2(T4, vc1, ws.y);
            float Sx = f2lo(S) + f2hi(S);
            float Sy = (f2lo(T3) + f2hi(T3)) - (f2lo(T4) + f2hi(T4));
            float r = mufu_rsqrt(fmaxf(Sx * Sx + Sy * Sy, 1e-30f));
            int d = co * 224 + dst;
            s_h1c[d] = Sx * r;
            s_h1s[d] = Sy * r;
        }
    }
    __syncthreads();

    // ---- Stage 2: conv2 4x4 s2 -> 288 outputs; 144 threads x 2 outputs ----
    int st = tid + ((blockIdx.x & 3) << 5);   // rotate active window across SMSPs
    if (st >= 320) st -= 320;
    if (st < 144) {
        int co = st & 7, q = st >> 3;          // co fastest -> v broadcast in 8-lane groups
        int ho = q / 3, wp = q % 3;            // outputs wo = 2wp, 2wp+1
        const int vb0 = ho * 32 + wp * 4;      // divisible by 4 -> 16B aligned
        const int wb0 = co * 68;
        ull SA = 0, TA3 = 0, TA4 = 0, SB = 0, TB3 = 0, TB4 = 0;
#pragma unroll
        for (int c = 0; c < 4; c++) {
#pragma unroll
            for (int i = 0; i < 4; i++) {
                int vb = c * 224 + vb0 + i * 16;            // multiple of 4
                ulonglong2 VC = *(const ulonglong2*)&s_h1c[vb];   // taps 0-3 cos
                ull vc2 = *(const ull*)&s_h1c[vb + 4];            // taps 4-5 cos
                ulonglong2 VS = *(const ulonglong2*)&s_h1s[vb];   // taps 0-3 sin
                ull vs2 = *(const ull*)&s_h1s[vb + 4];            // taps 4-5 sin
                int wb = wb0 + c * 16 + i * 4;
                ulonglong2 wc = *(const ulonglong2*)&s_w2c[wb];
                ulonglong2 ws = *(const ulonglong2*)&s_w2s[wb];
                // output A: px 0..3
                ffma2(SA,  VC.x, wc.x); ffma2(SA,  VC.y, wc.y);
                ffma2(SA,  VS.x, ws.x); ffma2(SA,  VS.y, ws.y);
                ffma2(TA3, VS.x, wc.x); ffma2(TA3, VS.y, wc.y);
                ffma2(TA4, VC.x, ws.x); ffma2(TA4, VC.y, ws.y);
                // output B: px 2..5
                ffma2(SB,  VC.y, wc.x); ffma2(SB,  vc2, wc.y);
                ffma2(SB,  VS.y, ws.x); ffma2(SB,  vs2, ws.y);
                ffma2(TB3, VS.y, wc.x); ffma2(TB3, vs2, wc.y);
                ffma2(TB4, VC.y, ws.x); ffma2(TB4, vc2, ws.y);
            }
        }
        int d0 = (ho * 6 + 2 * wp) * 8 + co;
        {
            float Sx = f2lo(SA) + f2hi(SA);
            float Sy = (f2lo(TA3) + f2hi(TA3)) - (f2lo(TA4) + f2hi(TA4));
            float r = mufu_rsqrt(fmaxf(Sx * Sx + Sy * Sy, 1e-30f));
            s_h2[d0] = make_float2(Sx * r, Sy * r);
        }
        {
            float Sx = f2lo(SB) + f2hi(SB);
            float Sy = (f2lo(TB3) + f2hi(TB3)) - (f2lo(TB4) + f2hi(TB4));
            float r = mufu_rsqrt(fmaxf(Sx * Sx + Sy * Sy, 1e-30f));
            s_h2[d0 + 8] = make_float2(Sx * r, Sy * r);
        }
    }
    __syncthreads();

    // ---- Stage 3: FF ring, one warp per class; quad taps, 1 LDG.128 each ----
    int o = tid >> 5, lane = tid & 31;
    const ulonglong2* wfo = reinterpret_cast<const ulonglong2*>(g_wfq + o * 288);
    ull S = 0, T = 0;
#pragma unroll
    for (int f = lane, k = 0; k < 9; k++, f += 32) {
        ull a = *(const ull*)&s_h2[f];
        ulonglong2 w = __ldg(wfo + f);
        ffma2(S, a, w.x);   // (c*wc, s*ws) -> Sx = lo+hi
        ffma2(T, a, w.y);   // (c*ws, s*wc) -> Sy = hi-lo
    }
    float Sx = f2lo(S) + f2hi(S);
    float Sy = f2hi(T) - f2lo(T);
#pragma unroll
    for (int off = 16; off; off >>= 1) {
        Sx += __shfl_xor_sync(0xffffffff, Sx, off);
        Sy += __shfl_xor_sync(0xffffffff, Sy, off);
    }
    if (lane == 0)
        out[(size_t)blockIdx.x * 10 + o] = Sy * mufu_rsqrt(fmaxf(Sx * Sx + Sy * Sy, 1e-30f));
}

extern "C" void kernel_launch(void* const* d_in, const int* in_sizes, int n_in,
                              void* d_out, int out_size) {
    const float* x  = (const float*)d_in[0];
    const float* w1 = (const float*)d_in[1];
    const float* w2 = (const float*)d_in[2];
    const float* wf = (const float*)d_in[3];
    float* out = (float*)d_out;
    int B = in_sizes[0] / 784;
    prep_kernel<<<6, 512>>>(w1, w2, wf);
    ring_kernel<<<B, 320>>>(x, out);
}